// round 8
// baseline (speedup 1.0000x reference)
#include <cuda_runtime.h>
#include <math.h>
#include <stdint.h>

#define BS   4096
#define L    20
#define NF   128
#define DM   640
#define DIN  512
#define DH   320
#define NB3  384

// ---------------- scratch ----------------
__device__ float g_last [BS*DIN];
__device__ float g_wctx [BS*2*DM];
__device__ float g_qh2  [BS*NB3];
__device__ float g_A2   [BS*512];
__device__ float g_hpl  [BS*NF];
__device__ float g_gi   [BS*3*NF];
__device__ float g_gh   [BS*3*NF];
__device__ float g_hpr  [BS*NF];
__device__ float g_q2   [2*DM];
__device__ float g_G3   [NF*2*DM];     // (128,1280)
__device__ float g_G4   [NB3*2*DM];    // (384,1280)
__device__ float g_b3   [NF];
__device__ float g_b4   [NB3];
__device__ float g_Wcmb [512*NF];      // (512,128) K x N

__device__ __forceinline__ unsigned f2tf(float v) {
    unsigned r;
    asm("cvt.rna.tf32.f32 %0, %1;" : "=r"(r) : "f"(v));
    return r;
}

__device__ __forceinline__ void mma_tf32(float c[4], unsigned a0, unsigned a1,
                                         unsigned a2, unsigned a3,
                                         unsigned b0, unsigned b1) {
    asm volatile(
        "mma.sync.aligned.m16n8k8.row.col.f32.tf32.tf32.f32 "
        "{%0,%1,%2,%3}, {%4,%5,%6,%7}, {%8,%9}, {%0,%1,%2,%3};"
        : "+f"(c[0]), "+f"(c[1]), "+f"(c[2]), "+f"(c[3])
        : "r"(a0), "r"(a1), "r"(a2), "r"(a3), "r"(b0), "r"(b1));
}

// ---------------- tf32 mma.sync GEMM, double-buffered (round-6 proven core) ----------------
// BT=1: C = A @ B^T + bias (B is (N,K) at ldb). BT=0: C = A @ B (B is (K,N) at ldb).
template<int BT, int ACT>
__global__ __launch_bounds__(256, 2) void gemm_tc(
    const float* __restrict__ A, int lda,
    const float* __restrict__ B, int ldb,
    const float* __restrict__ bias,
    float* __restrict__ C, int ldc,
    int M, int N, int K)
{
    __shared__ __align__(16) unsigned As[2*2048];
    __shared__ __align__(16) unsigned Bs[2*2048];
    const int bm = blockIdx.y * 128;
    const int bn = blockIdx.x * 128;
    const int t  = threadIdx.x;
    const int lane = t & 31;
    const int wr = (t >> 5) >> 2;
    const int wc = (t >> 5) & 3;

    const int ma = t >> 2, ca = t & 3;
    const float* Ag = A + (size_t)(bm + ma) * lda + ca * 4;
    const float* Bg;
    int kb = 0, nb4 = 0, nbr = 0, cb = 0;
    if (BT) { nbr = t >> 2; cb = t & 3; Bg = B + (size_t)(bn + nbr) * ldb + cb * 4; }
    else    { kb = t >> 5; nb4 = t & 31; Bg = B + (size_t)kb * ldb + bn + nb4 * 4; }

    float4 ra0, ra1, rb0, rb1;
    auto ldg = [&]() {
        ra0 = *(const float4*)Ag;
        ra1 = *(const float4*)(Ag + (size_t)64 * lda);
        Ag += 16;
        if (BT) {
            rb0 = *(const float4*)Bg;
            rb1 = *(const float4*)(Bg + (size_t)64 * ldb);
            Bg += 16;
        } else {
            rb0 = *(const float4*)Bg;
            rb1 = *(const float4*)(Bg + (size_t)8 * ldb);
            Bg += (size_t)16 * ldb;
        }
    };

    const int imA = ma >> 4, rA = ma & 15, gA = rA & 7, hiA = rA >> 3;
    const int sA = ca >> 1, k2A = ca & 1;
    const int baseA0 = (((sA * 8 + imA)     * 32 + gA * 4) * 4) + k2A * 2 + hiA;
    const int baseA1 = (((sA * 8 + imA + 4) * 32 + gA * 4) * 4) + k2A * 2 + hiA;

    auto sts = [&](int buf) {
        unsigned* Ab = As + buf * 2048;
        unsigned* Bb = Bs + buf * 2048;
        const float* v0 = &ra0.x; const float* v1 = &ra1.x;
        #pragma unroll
        for (int j = 0; j < 4; j++) {
            Ab[baseA0 + 4*j] = f2tf(v0[j]);
            Ab[baseA1 + 4*j] = f2tf(v1[j]);
        }
        if (BT) {
            const int g = nbr & 7, jn0 = (nbr >> 3), jn1 = jn0 + 8;
            const int sB = cb >> 1, regB = cb & 1;
            const int b0 = ((sB * 16 + jn0) * 32 + g * 4) * 2 + regB;
            const int b1 = ((sB * 16 + jn1) * 32 + g * 4) * 2 + regB;
            const float* w0 = &rb0.x; const float* w1 = &rb1.x;
            #pragma unroll
            for (int j = 0; j < 4; j++) {
                Bb[b0 + 2*j] = f2tf(w0[j]);
                Bb[b1 + 2*j] = f2tf(w1[j]);
            }
        } else {
            const int jn = nb4 >> 1, gb = (nb4 & 1) * 4;
            const int tig = kb & 3, regB = (kb >> 2) & 1;
            const int b0 = ((0 * 16 + jn) * 32 + gb * 4 + tig) * 2 + regB;
            const int b1 = ((1 * 16 + jn) * 32 + gb * 4 + tig) * 2 + regB;
            const float* w0 = &rb0.x; const float* w1 = &rb1.x;
            #pragma unroll
            for (int j = 0; j < 4; j++) {
                Bb[b0 + 8*j] = f2tf(w0[j]);
                Bb[b1 + 8*j] = f2tf(w1[j]);
            }
        }
    };

    float acc[4][4][4] = {};
    auto domma = [&](int buf) {
        const unsigned* Ab = As + buf * 2048;
        const unsigned* Bb = Bs + buf * 2048;
        #pragma unroll
        for (int s = 0; s < 2; s++) {
            uint4 af[4]; uint2 bf[4];
            #pragma unroll
            for (int i = 0; i < 4; i++)
                af[i] = *(const uint4*)&Ab[((s*8 + wr*4 + i) * 32 + lane) * 4];
            #pragma unroll
            for (int j = 0; j < 4; j++)
                bf[j] = *(const uint2*)&Bb[((s*16 + wc*4 + j) * 32 + lane) * 2];
            #pragma unroll
            for (int i = 0; i < 4; i++)
                #pragma unroll
                for (int j = 0; j < 4; j++)
                    mma_tf32(acc[i][j], af[i].x, af[i].y, af[i].z, af[i].w,
                             bf[j].x, bf[j].y);
        }
    };

    const int niter = K >> 4;
    ldg();
    sts(0);
    if (niter > 1) ldg();
    __syncthreads();
    for (int it = 0; it < niter; it++) {
        domma(it & 1);
        if (it + 1 < niter) {
            sts((it + 1) & 1);
            if (it + 2 < niter) ldg();
        }
        __syncthreads();
    }

    const int g = lane >> 2, tig = lane & 3;
    #pragma unroll
    for (int i = 0; i < 4; i++) {
        int row = bm + wr * 64 + i * 16 + g;
        #pragma unroll
        for (int j = 0; j < 4; j++) {
            int col = bn + wc * 32 + j * 8 + tig * 2;
            float b0 = bias ? bias[col] : 0.f;
            float b1 = bias ? bias[col + 1] : 0.f;
            float v00 = acc[i][j][0] + b0, v01 = acc[i][j][1] + b1;
            float v10 = acc[i][j][2] + b0, v11 = acc[i][j][3] + b1;
            if (ACT == 1) { v00 = tanhf(v00); v01 = tanhf(v01);
                            v10 = tanhf(v10); v11 = tanhf(v11); }
            *(float2*)(C + (size_t)row * ldc + col)       = make_float2(v00, v01);
            *(float2*)(C + (size_t)(row + 8) * ldc + col) = make_float2(v10, v11);
        }
    }
}

// ---------------- prep_q ----------------
__global__ void prep_q(const float* __restrict__ ipw, const float* __restrict__ ipb,
                       const float* __restrict__ time_b, float* __restrict__ q2)
{
    __shared__ float tc[NF];
    __shared__ float q0s[DH];
    int h = blockIdx.x, t = threadIdx.x;
    if (t < NF) tc[t] = cosf(time_b[t]);
    __syncthreads();
    if (t < DH) {
        int e = h*DH + t;
        float acc = ipb[e];
        const float* row = ipw + (size_t)e * DM + DIN;
        for (int k = 0; k < NF; k++) acc += tc[k] * row[k];
        q0s[t] = acc;
    }
    __syncthreads();
    float acc = 0.f;
    const float* base = ipw + (size_t)(DM + h*DH) * DM + t;
    for (int d = 0; d < DH; d++) acc += q0s[d] * base[(size_t)d * DM];
    q2[h*DM + t] = acc;
}

// ---------------- prep_G: G3 rows, b3, Wcmb ----------------
__global__ __launch_bounds__(256) void prep_G(
    const float* __restrict__ ipw, const float* __restrict__ ipb,
    const float* __restrict__ opw, const float* __restrict__ opb,
    const float* __restrict__ wf, const float* __restrict__ bf,
    const float* __restrict__ wq, const float* __restrict__ wv,
    const float* __restrict__ mw,
    float* __restrict__ G3, float* __restrict__ b3, float* __restrict__ Wcmb)
{
    int i = blockIdx.x, t = threadIdx.x;
    if (i >= 128) {
        int r = i - 128;
        if (r < 384) {
            if (t < NF) {
                float acc = 0.f;
                const float* wvr = wv + (size_t)r * NF;
                for (int k = 0; k < NF; k++) acc += wvr[k] * mw[k * NF + t];
                Wcmb[(size_t)r * NF + t] = acc;
            }
        } else {
            int r2 = r - 384;
            if (t < NF) Wcmb[(size_t)(384 + r2) * NF + t] = mw[(NF + r2) * NF + t];
        }
        return;
    }
    __shared__ float wqc[NF];
    __shared__ float b1s[NF];
    __shared__ float t2[DM];
    __shared__ float gt[DM];
    __shared__ float red[256];
    if (t < NF) {
        wqc[t] = wq[t * NF + i];
        float acc = bf[t];
        const float* row = wf + (size_t)t * DM;
        for (int m = 0; m < DM; m++) acc += row[m] * opb[m];
        b1s[t] = acc;
    }
    __syncthreads();
    for (int j = t; j < DM; j += 256) {
        float acc = 0.f;
        for (int q = 0; q < NF; q++) acc += wqc[q] * wf[(size_t)q * DM + j];
        t2[j] = acc;
    }
    __syncthreads();
    for (int d = t; d < DM; d += 256) {
        float acc = 0.f;
        for (int m = 0; m < DM; m++) acc += t2[m] * opw[(size_t)m * DM + d];
        gt[d] = acc;
    }
    __syncthreads();
    for (int c = t; c < 2*DM; c += 256) {
        int h = c / DM, cc = c - h*DM;
        float acc = 0.f;
        const float* base = ipw + (size_t)(2*DM + h*DH) * DM + cc;
        const float* gth = gt + h*DH;
        for (int dd = 0; dd < DH; dd++) acc += gth[dd] * base[(size_t)dd * DM];
        G3[(size_t)i * (2*DM) + c] = acc;
    }
    float p = 0.f;
    for (int d = t; d < DM; d += 256) p += gt[d] * ipb[2*DM + d];
    if (t < NF) p += b1s[t] * wqc[t];
    red[t] = p;
    __syncthreads();
    if (t == 0) {
        float s = 0.f;
        for (int k = 0; k < 256; k++) s += red[k];
        b3[i] = s;
    }
}

// ---------------- prep_b4: b4 = attn_wk^T-row dot b3 ----------------
__global__ void prep_b4(const float* __restrict__ wk, const float* __restrict__ b3,
                        float* __restrict__ b4)
{
    __shared__ float b3s[NF];
    int t = threadIdx.x;             // 384
    if (t < NF) b3s[t] = b3[t];
    __syncthreads();
    float acc = 0.f;
    const float* row = wk + (size_t)t * NF;
    for (int j = 0; j < NF; j++) acc += row[j] * b3s[j];
    b4[t] = acc;
}

// ---------------- MHA stage ----------------
#define MHA2_SMEM ((L*DM + 2*DM + 64) * 4 + L*5*4)
__global__ __launch_bounds__(256) void mha2_kernel(
    const int* __restrict__ nids, const int* __restrict__ hist_nids,
    const int* __restrict__ anon_ids, const int* __restrict__ hist_eids,
    const float* __restrict__ hist_ts, const int* __restrict__ hist_dirs,
    const float* __restrict__ node_feat, const float* __restrict__ edge_feat,
    const float* __restrict__ anony_emb, const float* __restrict__ time_w,
    const float* __restrict__ time_b, const float* __restrict__ q2,
    float* __restrict__ wctx, float* __restrict__ last)
{
    extern __shared__ float sm[];
    float* rows = sm;
    float* q2s  = sm + L*DM;
    float* sc   = q2s + 2*DM;
    int*   hn   = (int*)(sc + 64);
    int*   eid  = hn + L;
    int*   aid  = eid + L;
    int*   dirr = aid + L;
    float* dts  = (float*)(dirr + L);

    int b = blockIdx.x, t = threadIdx.x;
    if (t < L) {
        hn[t]  = hist_nids[b*L + t];
        eid[t] = hist_eids[b*L + t];
        aid[t] = anon_ids[b*L + t];
        dirr[t] = hist_dirs[b*L + t];
        dts[t] = hist_ts[b*L + L-1] - hist_ts[b*L + t];
    }
    for (int i = t; i < 2*DM; i += 256) q2s[i] = q2[i];
    __syncthreads();
    int nid = nids[b];

    for (int idx = t; idx < L*DM; idx += 256) {
        int m = idx / DM, d = idx - m*DM;
        float v;
        if (d < NF) {
            int src = dirr[m] ? nid : hn[m];
            v = node_feat[(size_t)src*NF + d];
        } else if (d < 2*NF) {
            int dst = dirr[m] ? hn[m] : nid;
            v = node_feat[(size_t)dst*NF + (d - NF)];
        } else if (d < 3*NF) {
            v = anony_emb[(size_t)aid[m]*NF + (d - 2*NF)];
        } else if (d < 4*NF) {
            v = edge_feat[(size_t)eid[m]*NF + (d - 3*NF)];
        } else {
            int f = d - 4*NF;
            v = cosf(fmaf(dts[m], time_w[f], time_b[f]));
        }
        if (m == L-1 && d < DIN) {
            last[(size_t)b*DIN + d] = v;
            v = 0.f;
        }
        rows[idx] = v;
    }
    __syncthreads();

    int w = t >> 5, lane = t & 31;
    for (int p = w; p < 2*L; p += 8) {
        int h = p / L, m = p - h*L;
        const float* qp = q2s + h*DM;
        const float* rp = rows + m*DM;
        float s = 0.f;
        for (int d = lane; d < DM; d += 32) s += qp[d] * rp[d];
        #pragma unroll
        for (int o = 16; o; o >>= 1) s += __shfl_xor_sync(0xffffffffu, s, o);
        if (lane == 0) {
            bool msk = (hn[m] == 0) && (m != L-1);
            sc[h*L + m] = msk ? -1e9f : s * (1.f / sqrtf((float)DH));
        }
    }
    __syncthreads();
    if (t < 2) {
        float mx = -1e30f;
        for (int m = 0; m < L; m++) mx = fmaxf(mx, sc[t*L + m]);
        float sum = 0.f;
        for (int m = 0; m < L; m++) { float e = expf(sc[t*L + m] - mx); sc[t*L + m] = e; sum += e; }
        float inv = 1.f / sum;
        for (int m = 0; m < L; m++) sc[t*L + m] *= inv;
    }
    __syncthreads();
    for (int i = t; i < 2*DM; i += 256) {
        int h = i / DM, d = i - h*DM;
        float acc = 0.f;
        #pragma unroll
        for (int m = 0; m < L; m++) acc += sc[h*L + m] * rows[m*DM + d];
        wctx[(size_t)b*(2*DM) + i] = acc;
    }
}

// ---------------- pooling attention stage ----------------
#define ATT2_SMEM ((L*NB3 + NB3 + 32) * 4 + L*3*4)
__global__ __launch_bounds__(128) void attn2_kernel(
    const int* __restrict__ nids, const int* __restrict__ hist_nids,
    const int* __restrict__ hist_eids, const float* __restrict__ hist_ts,
    const float* __restrict__ node_feat, const float* __restrict__ edge_feat,
    const float* __restrict__ time_w, const float* __restrict__ time_b,
    const float* __restrict__ qh2,
    float* __restrict__ A2)
{
    extern __shared__ float sm[];
    float* rows = sm;
    float* qs   = sm + L*NB3;
    float* a    = qs + NB3;
    int*   hn   = (int*)(a + 32);
    int*   eid  = hn + L;
    float* dts  = (float*)(eid + L);

    int b = blockIdx.x, t = threadIdx.x;
    if (t < L) {
        hn[t]  = hist_nids[b*L + t];
        eid[t] = hist_eids[b*L + t];
        dts[t] = hist_ts[b*L + L-1] - hist_ts[b*L + t];
    }
    for (int i = t; i < NB3; i += 128) qs[i] = qh2[(size_t)b*NB3 + i];
    __syncthreads();

    for (int idx = t; idx < L*NB3; idx += 128) {
        int m = idx / NB3, d = idx - m*NB3;
        float v;
        if (d < NF)          v = node_feat[(size_t)hn[m]*NF + d];
        else if (d < 2*NF)   v = edge_feat[(size_t)eid[m]*NF + (d - NF)];
        else {
            int f = d - 2*NF;
            v = cosf(fmaf(dts[m], time_w[f], time_b[f]));
        }
        rows[idx] = v;
    }
    __syncthreads();

    int w = t >> 5, lane = t & 31;
    for (int l = w; l < L; l += 4) {
        const float* rp = rows + l*NB3;
        float s = 0.f;
        for (int d = lane; d < NB3; d += 32) s += qs[d] * rp[d];
        #pragma unroll
        for (int o = 16; o; o >>= 1) s += __shfl_xor_sync(0xffffffffu, s, o);
        if (lane == 0) {
            bool msk = (hn[l] == 0) && (l != L-1);
            a[l] = msk ? -1e9f : s * (1.f / sqrtf((float)NF));
        }
    }
    __syncthreads();
    if (t == 0) {
        float mx = -1e30f;
        for (int l = 0; l < L; l++) mx = fmaxf(mx, a[l]);
        float sum = 0.f;
        for (int l = 0; l < L; l++) { float e = expf(a[l] - mx); a[l] = e; sum += e; }
        float inv = 1.f / sum;
        for (int l = 0; l < L; l++) a[l] *= inv;
    }
    __syncthreads();
    for (int d = t; d < NB3; d += 128) {
        float acc = 0.f;
        #pragma unroll
        for (int l = 0; l < L; l++) acc += a[l] * rows[l*NB3 + d];
        A2[(size_t)b*512 + d] = acc;
    }
    A2[(size_t)b*512 + NB3 + t] = node_feat[(size_t)nids[b]*NF + t];
}

// ---------------- GRU ----------------
__global__ void gru_kernel(const float* __restrict__ gi, const float* __restrict__ gh,
                           const float* __restrict__ hpl, float* __restrict__ hpr)
{
    int idx = blockIdx.x * blockDim.x + threadIdx.x;
    if (idx >= BS*NF) return;
    int b = idx / NF, f = idx - b*NF;
    const float* gib = gi + (size_t)b*3*NF;
    const float* ghb = gh + (size_t)b*3*NF;
    float r = 1.f / (1.f + expf(-(gib[f]      + ghb[f])));
    float z = 1.f / (1.f + expf(-(gib[NF + f] + ghb[NF + f])));
    float n = tanhf(gib[2*NF + f] + r * ghb[2*NF + f]);
    hpr[idx] = (1.f - z) * n + z * hpl[idx];
}

// ---------------- RK4 ODE, 4 rows per block ----------------
#define OB 4
#define ODE_SMEM ((128*129 + OB*128) * 4)
__global__ __launch_bounds__(128) void ode_kernel(
    const float* __restrict__ hpr, const float* __restrict__ ode_w,
    const float* __restrict__ ode_b, const float* __restrict__ tnode_w,
    const float* __restrict__ tnode_b, const float* __restrict__ hist_ts,
    float* __restrict__ out)
{
    extern __shared__ float sm[];
    float* Wsm = sm;
    float* vs  = sm + 128*129;
    int b0 = blockIdx.x * OB, f = threadIdx.x;
    for (int i = f; i < NF*NF; i += 128) Wsm[(i >> 7)*129 + (i & 127)] = ode_w[i];
    float t0[OB], ratio[OB], z[OB], h0[OB], t1[OB];
    #pragma unroll
    for (int r = 0; r < OB; r++) {
        int b = b0 + r;
        t0[r] = hist_ts[b*L + L-2];
        t1[r] = hist_ts[b*L + L-1];
        ratio[r] = t1[r] - t0[r];
        h0[r] = hpr[(size_t)b*NF + f];
        z[r] = h0[r];
    }
    float twf = tnode_w[f], tbf = tnode_b[f], obf = ode_b[f];
    __syncthreads();
    float w[NF];
    #pragma unroll
    for (int k = 0; k < NF; k++) w[k] = Wsm[f*129 + k];
    __syncthreads();

    auto feval = [&](float s, const float* zin, float* kout) {
        #pragma unroll
        for (int r = 0; r < OB; r++) {
            float t = fmaf(s, ratio[r], t0[r]);
            vs[r*128 + f] = zin[r] + cosf(fmaf(t, twf, tbf));
        }
        __syncthreads();
        float acc[OB];
        #pragma unroll
        for (int r = 0; r < OB; r++) acc[r] = obf;
        #pragma unroll 8
        for (int k = 0; k < NF; k += 4) {
            #pragma unroll
            for (int r = 0; r < OB; r++) {
                float4 v = *(const float4*)&vs[r*128 + k];
                acc[r] += v.x * w[k] + v.y * w[k+1] + v.z * w[k+2] + v.w * w[k+3];
            }
        }
        __syncthreads();
        #pragma unroll
        for (int r = 0; r < OB; r++) kout[r] = tanhf(acc[r]) * ratio[r];
    };

    const float ds = 0.125f;
    float k1[OB], k2[OB], k3[OB], k4[OB], ztmp[OB];
    for (int st = 0; st < 8; st++) {
        float s = st * ds;
        feval(s, z, k1);
        #pragma unroll
        for (int r = 0; r < OB; r++) ztmp[r] = z[r] + 0.5f*ds*k1[r];
        feval(s + 0.5f*ds, ztmp, k2);
        #pragma unroll
        for (int r = 0; r < OB; r++) ztmp[r] = z[r] + 0.5f*ds*k2[r];
        feval(s + 0.5f*ds, ztmp, k3);
        #pragma unroll
        for (int r = 0; r < OB; r++) ztmp[r] = z[r] + ds*k3[r];
        feval(s + ds, ztmp, k4);
        #pragma unroll
        for (int r = 0; r < OB; r++)
            z[r] += ds * (1.f/6.f) * (k1[r] + 2.f*k2[r] + 2.f*k3[r] + k4[r]);
    }
    #pragma unroll
    for (int r = 0; r < OB; r++) {
        int b = b0 + r;
        out[(size_t)b*NF + f] = z[r];
        out[(size_t)BS*NF + (size_t)b*NF + f] = h0[r];
        if (f == 0) out[(size_t)2*BS*NF + b] = t1[r];
    }
}

// ---------------- launch ----------------
extern "C" void kernel_launch(void* const* d_in, const int* in_sizes, int n_in,
                              void* d_out, int out_size)
{
    const int*   nids      = (const int*)  d_in[0];
    const int*   hist_nids = (const int*)  d_in[2];
    const int*   anon      = (const int*)  d_in[3];
    const int*   eids      = (const int*)  d_in[4];
    const float* hist_ts   = (const float*)d_in[5];
    const int*   dirs      = (const int*)  d_in[6];
    const float* node_feat = (const float*)d_in[7];
    const float* edge_feat = (const float*)d_in[8];
    const float* anony_emb = (const float*)d_in[9];
    const float* time_w    = (const float*)d_in[10];
    const float* time_b    = (const float*)d_in[11];
    const float* in_proj_w = (const float*)d_in[12];
    const float* in_proj_b = (const float*)d_in[13];
    const float* out_proj_w= (const float*)d_in[14];
    const float* out_proj_b= (const float*)d_in[15];
    const float* outfn_w   = (const float*)d_in[16];
    const float* outfn_b   = (const float*)d_in[17];
    const float* attn_wq   = (const float*)d_in[18];
    const float* attn_wk   = (const float*)d_in[19];
    const float* attn_wv   = (const float*)d_in[20];
    const float* merge_w   = (const float*)d_in[21];
    const float* merge_b   = (const float*)d_in[22];
    const float* gru_w_ih  = (const float*)d_in[23];
    const float* gru_w_hh  = (const float*)d_in[24];
    const float* gru_b_ih  = (const float*)d_in[25];
    const float* gru_b_hh  = (const float*)d_in[26];
    const float* ode_w     = (const float*)d_in[27];
    const float* ode_b     = (const float*)d_in[28];
    const float* tnode_w   = (const float*)d_in[29];
    const float* tnode_b   = (const float*)d_in[30];
    float* out = (float*)d_out;

    float *p_last, *p_wctx, *p_qh2, *p_A2, *p_hpl, *p_gi, *p_gh, *p_hpr,
          *p_q2, *p_G3, *p_G4, *p_b3, *p_b4, *p_Wcmb;
    cudaGetSymbolAddress((void**)&p_last, g_last);
    cudaGetSymbolAddress((void**)&p_wctx, g_wctx);
    cudaGetSymbolAddress((void**)&p_qh2,  g_qh2);
    cudaGetSymbolAddress((void**)&p_A2,   g_A2);
    cudaGetSymbolAddress((void**)&p_hpl,  g_hpl);
    cudaGetSymbolAddress((void**)&p_gi,   g_gi);
    cudaGetSymbolAddress((void**)&p_gh,   g_gh);
    cudaGetSymbolAddress((void**)&p_hpr,  g_hpr);
    cudaGetSymbolAddress((void**)&p_q2,   g_q2);
    cudaGetSymbolAddress((void**)&p_G3,   g_G3);
    cudaGetSymbolAddress((void**)&p_G4,   g_G4);
    cudaGetSymbolAddress((void**)&p_b3,   g_b3);
    cudaGetSymbolAddress((void**)&p_b4,   g_b4);
    cudaGetSymbolAddress((void**)&p_Wcmb, g_Wcmb);

    cudaFuncSetAttribute(mha2_kernel, cudaFuncAttributeMaxDynamicSharedMemorySize, MHA2_SMEM);
    cudaFuncSetAttribute(attn2_kernel, cudaFuncAttributeMaxDynamicSharedMemorySize, ATT2_SMEM);
    cudaFuncSetAttribute(ode_kernel, cudaFuncAttributeMaxDynamicSharedMemorySize, ODE_SMEM);

    // --- prep ---
    prep_q<<<2, DM>>>(in_proj_w, in_proj_b, time_b, p_q2);
    prep_G<<<640, 256>>>(in_proj_w, in_proj_b, out_proj_w, out_proj_b,
                         outfn_w, outfn_b, attn_wq, attn_wv, merge_w,
                         p_G3, p_b3, p_Wcmb);
    prep_b4<<<1, NB3>>>(attn_wk, p_b3, p_b4);
    // G4 = attn_wk @ G3   (384 x 1280, K=128)
    gemm_tc<0,0><<<dim3(2*DM/128, NB3/128), 256>>>(
        attn_wk, NF, p_G3, 2*DM, nullptr, p_G4, 2*DM, NB3, 2*DM, NF);

    // --- main pipeline ---
    mha2_kernel<<<BS, 256, MHA2_SMEM>>>(nids, hist_nids, anon, eids, hist_ts, dirs,
                                        node_feat, edge_feat, anony_emb, time_w, time_b,
                                        p_q2, p_wctx, p_last);
    // qh2 = wctx @ G4^T + b4   (4096 x 384, K=1280)
    gemm_tc<1,0><<<dim3(NB3/128, BS/128), 256>>>(
        p_wctx, 2*DM, p_G4, 2*DM, p_b4, p_qh2, NB3, BS, NB3, 2*DM);
    attn2_kernel<<<BS, 128, ATT2_SMEM>>>(nids, hist_nids, eids, hist_ts,
                                         node_feat, edge_feat, time_w, time_b,
                                         p_qh2, p_A2);
    // hpl = tanh(A2 @ Wcmb + merge_b)   (4096 x 128, K=512)
    gemm_tc<0,1><<<dim3(1, BS/128), 256>>>(
        p_A2, 512, p_Wcmb, NF, merge_b, p_hpl, NF, BS, NF, 512);
    // gi = last @ gru_w_ih^T + b   (K=512)
    gemm_tc<1,0><<<dim3(3*NF/128, BS/128), 256>>>(
        p_last, DIN, gru_w_ih, DIN, gru_b_ih, p_gi, 3*NF, BS, 3*NF, DIN);
    // gh = hpl @ gru_w_hh^T + b    (K=128)
    gemm_tc<1,0><<<dim3(3*NF/128, BS/128), 256>>>(
        p_hpl, NF, gru_w_hh, NF, gru_b_hh, p_gh, 3*NF, BS, 3*NF, NF);
    gru_kernel<<<(BS*NF + 255)/256, 256>>>(p_gi, p_gh, p_hpl, p_hpr);
    ode_kernel<<<BS/OB, 128, ODE_SMEM>>>(p_hpr, ode_w, ode_b, tnode_w, tnode_b, hist_ts, out);
}

// round 9
// speedup vs baseline: 1.3782x; 1.3782x over previous
#include <cuda_runtime.h>
#include <math.h>
#include <stdint.h>

#define BS   4096
#define L    20
#define NF   128
#define DM   640
#define DIN  512
#define DH   320
#define NB3  384

// ---------------- scratch ----------------
__device__ float g_last [BS*DIN];
__device__ float g_wctx [BS*2*DM];
__device__ float g_qh   [BS*NF];
__device__ float g_qh2  [BS*NB3];
__device__ float g_A2   [BS*512];
__device__ float g_hpl  [BS*NF];
__device__ float g_gi   [BS*3*NF];
__device__ float g_gh   [BS*3*NF];
__device__ float g_hpr  [BS*NF];
__device__ float g_q2   [2*DM];
__device__ float g_G3   [NF*2*DM];     // (128,1280) N x K
__device__ float g_b3   [NF];
__device__ float g_WcmbT[NF*512];      // (128,512) N x K (transposed combined merge weight)

__device__ __forceinline__ unsigned f2tf(float v) {
    unsigned r;
    asm("cvt.rna.tf32.f32 %0, %1;" : "=r"(r) : "f"(v));
    return r;
}

__device__ __forceinline__ uint32_t smem_u32(const void* p) {
    uint32_t a;
    asm("{ .reg .u64 t; cvta.to.shared.u64 t, %1; cvt.u32.u64 %0, t; }" : "=r"(a) : "l"(p));
    return a;
}
static __device__ __forceinline__ void cp16(uint32_t s, const void* g) {
    asm volatile("cp.async.cg.shared.global [%0], [%1], 16;" :: "r"(s), "l"(g));
}

__device__ __forceinline__ void mma_tf32(float c[4], unsigned a0, unsigned a1,
                                         unsigned a2, unsigned a3,
                                         unsigned b0, unsigned b1) {
    asm volatile(
        "mma.sync.aligned.m16n8k8.row.col.f32.tf32.tf32.f32 "
        "{%0,%1,%2,%3}, {%4,%5,%6,%7}, {%8,%9}, {%0,%1,%2,%3};"
        : "+f"(c[0]), "+f"(c[1]), "+f"(c[2]), "+f"(c[3])
        : "r"(a0), "r"(a1), "r"(a2), "r"(a3), "r"(b0), "r"(b1));
}

// ---------------- tf32 GEMM: C = A @ B^T + bias, cp.async 3-stage (round-7 proven core) ----------------
// A: (M,K) stride lda. B: (N,K) stride ldb. M%128==0, N%128==0, K%16==0.
#define GS 3
#define STG_F (128*20)        // floats per operand tile (row stride 20)
#define GEMM_SMEM (GS*2*STG_F*4)

template<int ACT>
__global__ __launch_bounds__(256, 2) void gemm_tc(
    const float* __restrict__ A, int lda,
    const float* __restrict__ B, int ldb,
    const float* __restrict__ bias,
    float* __restrict__ C, int ldc,
    int M, int N, int K)
{
    extern __shared__ float smem[];
    const uint32_t smb = smem_u32(smem);
    const int bm = blockIdx.y * 128;
    const int bn = blockIdx.x * 128;
    const int t  = threadIdx.x;
    const int lane = t & 31;
    const int wr = (t >> 5) >> 2;    // 0..1
    const int wc = (t >> 5) & 3;     // 0..3
    const int g = lane >> 2, tig = lane & 3;

    const int niter = K >> 4;
    const float* Abase = A + (size_t)bm * lda;
    const float* Bbase = B + (size_t)bn * ldb;

    auto load_stage = [&](int s, int c) {
        uint32_t as = smb + (uint32_t)(s * 2 * STG_F) * 4;
        uint32_t bs = as + STG_F * 4;
        const float* Ac = Abase + c * 16;
        const float* Bc = Bbase + c * 16;
        #pragma unroll
        for (int i = 0; i < 2; i++) {
            int id = i * 256 + t;
            int row = id >> 2, seg = id & 3;
            cp16(as + (uint32_t)(row * 20 + seg * 4) * 4, Ac + (size_t)row * lda + seg * 4);
            cp16(bs + (uint32_t)(row * 20 + seg * 4) * 4, Bc + (size_t)row * ldb + seg * 4);
        }
    };

    float acc[4][4][4] = {};

    #pragma unroll
    for (int s = 0; s < GS - 1; s++) {
        if (s < niter) load_stage(s, s);
        asm volatile("cp.async.commit_group;" ::: "memory");
    }

    for (int c = 0; c < niter; c++) {
        asm volatile("cp.async.wait_group %0;" :: "n"(GS - 2) : "memory");
        __syncthreads();
        if (c + GS - 1 < niter) load_stage((c + GS - 1) % GS, c + GS - 1);
        asm volatile("cp.async.commit_group;" ::: "memory");

        const float* As  = smem + (c % GS) * 2 * STG_F;
        const float* Bsm = As + STG_F;
        #pragma unroll
        for (int s8 = 0; s8 < 2; s8++) {
            const int kk = s8 * 8;
            unsigned af[4][4]; unsigned bf[4][2];
            #pragma unroll
            for (int i = 0; i < 4; i++) {
                int r0 = (wr * 64 + i * 16 + g) * 20 + kk + tig;
                af[i][0] = f2tf(As[r0]);
                af[i][1] = f2tf(As[r0 + 8 * 20]);
                af[i][2] = f2tf(As[r0 + 4]);
                af[i][3] = f2tf(As[r0 + 8 * 20 + 4]);
            }
            #pragma unroll
            for (int j = 0; j < 4; j++) {
                int n0 = (wc * 32 + j * 8 + g) * 20 + kk + tig;
                bf[j][0] = f2tf(Bsm[n0]);
                bf[j][1] = f2tf(Bsm[n0 + 4]);
            }
            #pragma unroll
            for (int i = 0; i < 4; i++)
                #pragma unroll
                for (int j = 0; j < 4; j++)
                    mma_tf32(acc[i][j], af[i][0], af[i][1], af[i][2], af[i][3],
                             bf[j][0], bf[j][1]);
        }
    }

    #pragma unroll
    for (int i = 0; i < 4; i++) {
        int row = bm + wr * 64 + i * 16 + g;
        #pragma unroll
        for (int j = 0; j < 4; j++) {
            int col = bn + wc * 32 + j * 8 + tig * 2;
            float b0 = bias ? bias[col] : 0.f;
            float b1 = bias ? bias[col + 1] : 0.f;
            float v00 = acc[i][j][0] + b0, v01 = acc[i][j][1] + b1;
            float v10 = acc[i][j][2] + b0, v11 = acc[i][j][3] + b1;
            if (ACT == 1) { v00 = tanhf(v00); v01 = tanhf(v01);
                            v10 = tanhf(v10); v11 = tanhf(v11); }
            *(float2*)(C + (size_t)row * ldc + col)       = make_float2(v00, v01);
            *(float2*)(C + (size_t)(row + 8) * ldc + col) = make_float2(v10, v11);
        }
    }
}

// ---------------- prep_q ----------------
__global__ void prep_q(const float* __restrict__ ipw, const float* __restrict__ ipb,
                       const float* __restrict__ time_b, float* __restrict__ q2)
{
    __shared__ float tc[NF];
    __shared__ float q0s[DH];
    int h = blockIdx.x, t = threadIdx.x;
    if (t < NF) tc[t] = cosf(time_b[t]);
    __syncthreads();
    if (t < DH) {
        int e = h*DH + t;
        float acc = ipb[e];
        const float* row = ipw + (size_t)e * DM + DIN;
        for (int k = 0; k < NF; k++) acc += tc[k] * row[k];
        q0s[t] = acc;
    }
    __syncthreads();
    float acc = 0.f;
    const float* base = ipw + (size_t)(DM + h*DH) * DM + t;
    for (int d = 0; d < DH; d++) acc += q0s[d] * base[(size_t)d * DM];
    q2[h*DM + t] = acc;
}

// ---------------- prep_G: G3 rows, b3, WcmbT ----------------
__global__ __launch_bounds__(256) void prep_G(
    const float* __restrict__ ipw, const float* __restrict__ ipb,
    const float* __restrict__ opw, const float* __restrict__ opb,
    const float* __restrict__ wf, const float* __restrict__ bf,
    const float* __restrict__ wq, const float* __restrict__ wv,
    const float* __restrict__ mw,
    float* __restrict__ G3, float* __restrict__ b3, float* __restrict__ WcmbT)
{
    int i = blockIdx.x, t = threadIdx.x;
    if (i >= 128) {
        int r = i - 128;
        if (r < 384) {
            if (t < NF) {
                float acc = 0.f;
                const float* wvr = wv + (size_t)r * NF;
                for (int k = 0; k < NF; k++) acc += wvr[k] * mw[k * NF + t];
                WcmbT[(size_t)t * 512 + r] = acc;
            }
        } else {
            int r2 = r - 384;
            if (t < NF) WcmbT[(size_t)t * 512 + 384 + r2] = mw[(NF + r2) * NF + t];
        }
        return;
    }
    __shared__ float wqc[NF];
    __shared__ float b1s[NF];
    __shared__ float t2[DM];
    __shared__ float gt[DM];
    __shared__ float red[256];
    if (t < NF) {
        wqc[t] = wq[t * NF + i];
        float acc = bf[t];
        const float* row = wf + (size_t)t * DM;
        for (int m = 0; m < DM; m++) acc += row[m] * opb[m];
        b1s[t] = acc;
    }
    __syncthreads();
    for (int j = t; j < DM; j += 256) {
        float acc = 0.f;
        for (int q = 0; q < NF; q++) acc += wqc[q] * wf[(size_t)q * DM + j];
        t2[j] = acc;
    }
    __syncthreads();
    for (int d = t; d < DM; d += 256) {
        float acc = 0.f;
        for (int m = 0; m < DM; m++) acc += t2[m] * opw[(size_t)m * DM + d];
        gt[d] = acc;
    }
    __syncthreads();
    for (int c = t; c < 2*DM; c += 256) {
        int h = c / DM, cc = c - h*DM;
        float acc = 0.f;
        const float* base = ipw + (size_t)(2*DM + h*DH) * DM + cc;
        const float* gth = gt + h*DH;
        for (int dd = 0; dd < DH; dd++) acc += gth[dd] * base[(size_t)dd * DM];
        G3[(size_t)i * (2*DM) + c] = acc;
    }
    float p = 0.f;
    for (int d = t; d < DM; d += 256) p += gt[d] * ipb[2*DM + d];
    if (t < NF) p += b1s[t] * wqc[t];
    red[t] = p;
    __syncthreads();
    if (t == 0) {
        float s = 0.f;
        for (int k = 0; k < 256; k++) s += red[k];
        b3[i] = s;
    }
}

// ---------------- MHA stage ----------------
#define MHA2_SMEM ((L*DM + 2*DM + 64) * 4 + L*5*4)
__global__ __launch_bounds__(256) void mha2_kernel(
    const int* __restrict__ nids, const int* __restrict__ hist_nids,
    const int* __restrict__ anon_ids, const int* __restrict__ hist_eids,
    const float* __restrict__ hist_ts, const int* __restrict__ hist_dirs,
    const float* __restrict__ node_feat, const float* __restrict__ edge_feat,
    const float* __restrict__ anony_emb, const float* __restrict__ time_w,
    const float* __restrict__ time_b, const float* __restrict__ q2,
    float* __restrict__ wctx, float* __restrict__ last)
{
    extern __shared__ float sm[];
    float* rows = sm;
    float* q2s  = sm + L*DM;
    float* sc   = q2s + 2*DM;
    int*   hn   = (int*)(sc + 64);
    int*   eid  = hn + L;
    int*   aid  = eid + L;
    int*   dirr = aid + L;
    float* dts  = (float*)(dirr + L);

    int b = blockIdx.x, t = threadIdx.x;
    if (t < L) {
        hn[t]  = hist_nids[b*L + t];
        eid[t] = hist_eids[b*L + t];
        aid[t] = anon_ids[b*L + t];
        dirr[t] = hist_dirs[b*L + t];
        dts[t] = hist_ts[b*L + L-1] - hist_ts[b*L + t];
    }
    for (int i = t; i < 2*DM; i += 256) q2s[i] = q2[i];
    __syncthreads();
    int nid = nids[b];

    for (int idx = t; idx < L*DM; idx += 256) {
        int m = idx / DM, d = idx - m*DM;
        float v;
        if (d < NF) {
            int src = dirr[m] ? nid : hn[m];
            v = node_feat[(size_t)src*NF + d];
        } else if (d < 2*NF) {
            int dst = dirr[m] ? hn[m] : nid;
            v = node_feat[(size_t)dst*NF + (d - NF)];
        } else if (d < 3*NF) {
            v = anony_emb[(size_t)aid[m]*NF + (d - 2*NF)];
        } else if (d < 4*NF) {
            v = edge_feat[(size_t)eid[m]*NF + (d - 3*NF)];
        } else {
            int f = d - 4*NF;
            v = cosf(fmaf(dts[m], time_w[f], time_b[f]));
        }
        if (m == L-1 && d < DIN) {
            last[(size_t)b*DIN + d] = v;
            v = 0.f;
        }
        rows[idx] = v;
    }
    __syncthreads();

    int w = t >> 5, lane = t & 31;
    for (int p = w; p < 2*L; p += 8) {
        int h = p / L, m = p - h*L;
        const float* qp = q2s + h*DM;
        const float* rp = rows + m*DM;
        float s = 0.f;
        for (int d = lane; d < DM; d += 32) s += qp[d] * rp[d];
        #pragma unroll
        for (int o = 16; o; o >>= 1) s += __shfl_xor_sync(0xffffffffu, s, o);
        if (lane == 0) {
            bool msk = (hn[m] == 0) && (m != L-1);
            sc[h*L + m] = msk ? -1e9f : s * (1.f / sqrtf((float)DH));
        }
    }
    __syncthreads();
    if (t < 2) {
        float mx = -1e30f;
        for (int m = 0; m < L; m++) mx = fmaxf(mx, sc[t*L + m]);
        float sum = 0.f;
        for (int m = 0; m < L; m++) { float e = expf(sc[t*L + m] - mx); sc[t*L + m] = e; sum += e; }
        float inv = 1.f / sum;
        for (int m = 0; m < L; m++) sc[t*L + m] *= inv;
    }
    __syncthreads();
    for (int i = t; i < 2*DM; i += 256) {
        int h = i / DM, d = i - h*DM;
        float acc = 0.f;
        #pragma unroll
        for (int m = 0; m < L; m++) acc += sc[h*L + m] * rows[m*DM + d];
        wctx[(size_t)b*(2*DM) + i] = acc;
    }
}

// ---------------- pooling attention stage ----------------
#define ATT2_SMEM ((L*NB3 + NB3 + 32) * 4 + L*3*4)
__global__ __launch_bounds__(128) void attn2_kernel(
    const int* __restrict__ nids, const int* __restrict__ hist_nids,
    const int* __restrict__ hist_eids, const float* __restrict__ hist_ts,
    const float* __restrict__ node_feat, const float* __restrict__ edge_feat,
    const float* __restrict__ time_w, const float* __restrict__ time_b,
    const float* __restrict__ qh2,
    float* __restrict__ A2)
{
    extern __shared__ float sm[];
    float* rows = sm;
    float* qs   = sm + L*NB3;
    float* a    = qs + NB3;
    int*   hn   = (int*)(a + 32);
    int*   eid  = hn + L;
    float* dts  = (float*)(eid + L);

    int b = blockIdx.x, t = threadIdx.x;
    if (t < L) {
        hn[t]  = hist_nids[b*L + t];
        eid[t] = hist_eids[b*L + t];
        dts[t] = hist_ts[b*L + L-1] - hist_ts[b*L + t];
    }
    for (int i = t; i < NB3; i += 128) qs[i] = qh2[(size_t)b*NB3 + i];
    __syncthreads();

    for (int idx = t; idx < L*NB3; idx += 128) {
        int m = idx / NB3, d = idx - m*NB3;
        float v;
        if (d < NF)          v = node_feat[(size_t)hn[m]*NF + d];
        else if (d < 2*NF)   v = edge_feat[(size_t)eid[m]*NF + (d - NF)];
        else {
            int f = d - 2*NF;
            v = cosf(fmaf(dts[m], time_w[f], time_b[f]));
        }
        rows[idx] = v;
    }
    __syncthreads();

    int w = t >> 5, lane = t & 31;
    for (int l = w; l < L; l += 4) {
        const float* rp = rows + l*NB3;
        float s = 0.f;
        for (int d = lane; d < NB3; d += 32) s += qs[d] * rp[d];
        #pragma unroll
        for (int o = 16; o; o >>= 1) s += __shfl_xor_sync(0xffffffffu, s, o);
        if (lane == 0) {
            bool msk = (hn[l] == 0) && (l != L-1);
            a[l] = msk ? -1e9f : s * (1.f / sqrtf((float)NF));
        }
    }
    __syncthreads();
    if (t == 0) {
        float mx = -1e30f;
        for (int l = 0; l < L; l++) mx = fmaxf(mx, a[l]);
        float sum = 0.f;
        for (int l = 0; l < L; l++) { float e = expf(a[l] - mx); a[l] = e; sum += e; }
        float inv = 1.f / sum;
        for (int l = 0; l < L; l++) a[l] *= inv;
    }
    __syncthreads();
    for (int d = t; d < NB3; d += 128) {
        float acc = 0.f;
        #pragma unroll
        for (int l = 0; l < L; l++) acc += a[l] * rows[l*NB3 + d];
        A2[(size_t)b*512 + d] = acc;
    }
    A2[(size_t)b*512 + NB3 + t] = node_feat[(size_t)nids[b]*NF + t];
}

// ---------------- GRU ----------------
__global__ void gru_kernel(const float* __restrict__ gi, const float* __restrict__ gh,
                           const float* __restrict__ hpl, float* __restrict__ hpr)
{
    int idx = blockIdx.x * blockDim.x + threadIdx.x;
    if (idx >= BS*NF) return;
    int b = idx / NF, f = idx - b*NF;
    const float* gib = gi + (size_t)b*3*NF;
    const float* ghb = gh + (size_t)b*3*NF;
    float r = 1.f / (1.f + expf(-(gib[f]      + ghb[f])));
    float z = 1.f / (1.f + expf(-(gib[NF + f] + ghb[NF + f])));
    float n = tanhf(gib[2*NF + f] + r * ghb[2*NF + f]);
    hpr[idx] = (1.f - z) * n + z * hpl[idx];
}

// ---------------- RK4 ODE (round-6 proven, OB=1) ----------------
#define ODE_SMEM ((128*129 + 128) * 4)
__global__ __launch_bounds__(128) void ode_kernel(
    const float* __restrict__ hpr, const float* __restrict__ ode_w,
    const float* __restrict__ ode_b, const float* __restrict__ tnode_w,
    const float* __restrict__ tnode_b, const float* __restrict__ hist_ts,
    float* __restrict__ out)
{
    extern __shared__ float sm[];
    float* Wsm = sm;
    float* vs  = sm + 128*129;
    int b = blockIdx.x, f = threadIdx.x;
    for (int i = f; i < NF*NF; i += 128) Wsm[(i >> 7)*129 + (i & 127)] = ode_w[i];
    float t0 = hist_ts[b*L + L-2];
    float t1 = hist_ts[b*L + L-1];
    float ratio = t1 - t0;
    float twf = tnode_w[f], tbf = tnode_b[f], obf = ode_b[f];
    float h0 = hpr[(size_t)b*NF + f];
    float z = h0;
    __syncthreads();
    float w[NF];
    #pragma unroll
    for (int k = 0; k < NF; k++) w[k] = Wsm[f*129 + k];
    __syncthreads();

    auto feval = [&](float s, float zin) -> float {
        float t = fmaf(s, ratio, t0);
        vs[f] = zin + cosf(fmaf(t, twf, tbf));
        __syncthreads();
        float acc = obf;
        #pragma unroll
        for (int k = 0; k < NF; k += 4) {
            float4 v = *(const float4*)&vs[k];
            acc += v.x * w[k] + v.y * w[k+1] + v.z * w[k+2] + v.w * w[k+3];
        }
        __syncthreads();
        return tanhf(acc) * ratio;
    };

    const float ds = 0.125f;
    for (int st = 0; st < 8; st++) {
        float s = st * ds;
        float k1 = feval(s,            z);
        float k2 = feval(s + 0.5f*ds,  z + 0.5f*ds*k1);
        float k3 = feval(s + 0.5f*ds,  z + 0.5f*ds*k2);
        float k4 = feval(s + ds,       z + ds*k3);
        z += ds * (1.f/6.f) * (k1 + 2.f*k2 + 2.f*k3 + k4);
    }
    out[(size_t)b*NF + f] = z;
    out[(size_t)BS*NF + (size_t)b*NF + f] = h0;
    if (f == 0) out[(size_t)2*BS*NF + b] = t1;
}

// ---------------- launch ----------------
extern "C" void kernel_launch(void* const* d_in, const int* in_sizes, int n_in,
                              void* d_out, int out_size)
{
    const int*   nids      = (const int*)  d_in[0];
    const int*   hist_nids = (const int*)  d_in[2];
    const int*   anon      = (const int*)  d_in[3];
    const int*   eids      = (const int*)  d_in[4];
    const float* hist_ts   = (const float*)d_in[5];
    const int*   dirs      = (const int*)  d_in[6];
    const float* node_feat = (const float*)d_in[7];
    const float* edge_feat = (const float*)d_in[8];
    const float* anony_emb = (const float*)d_in[9];
    const float* time_w    = (const float*)d_in[10];
    const float* time_b    = (const float*)d_in[11];
    const float* in_proj_w = (const float*)d_in[12];
    const float* in_proj_b = (const float*)d_in[13];
    const float* out_proj_w= (const float*)d_in[14];
    const float* out_proj_b= (const float*)d_in[15];
    const float* outfn_w   = (const float*)d_in[16];
    const float* outfn_b   = (const float*)d_in[17];
    const float* attn_wq   = (const float*)d_in[18];
    const float* attn_wk   = (const float*)d_in[19];
    const float* attn_wv   = (const float*)d_in[20];
    const float* merge_w   = (const float*)d_in[21];
    const float* merge_b   = (const float*)d_in[22];
    const float* gru_w_ih  = (const float*)d_in[23];
    const float* gru_w_hh  = (const float*)d_in[24];
    const float* gru_b_ih  = (const float*)d_in[25];
    const float* gru_b_hh  = (const float*)d_in[26];
    const float* ode_w     = (const float*)d_in[27];
    const float* ode_b     = (const float*)d_in[28];
    const float* tnode_w   = (const float*)d_in[29];
    const float* tnode_b   = (const float*)d_in[30];
    float* out = (float*)d_out;

    float *p_last, *p_wctx, *p_qh, *p_qh2, *p_A2, *p_hpl, *p_gi, *p_gh, *p_hpr,
          *p_q2, *p_G3, *p_b3, *p_WcmbT;
    cudaGetSymbolAddress((void**)&p_last,  g_last);
    cudaGetSymbolAddress((void**)&p_wctx,  g_wctx);
    cudaGetSymbolAddress((void**)&p_qh,    g_qh);
    cudaGetSymbolAddress((void**)&p_qh2,   g_qh2);
    cudaGetSymbolAddress((void**)&p_A2,    g_A2);
    cudaGetSymbolAddress((void**)&p_hpl,   g_hpl);
    cudaGetSymbolAddress((void**)&p_gi,    g_gi);
    cudaGetSymbolAddress((void**)&p_gh,    g_gh);
    cudaGetSymbolAddress((void**)&p_hpr,   g_hpr);
    cudaGetSymbolAddress((void**)&p_q2,    g_q2);
    cudaGetSymbolAddress((void**)&p_G3,    g_G3);
    cudaGetSymbolAddress((void**)&p_b3,    g_b3);
    cudaGetSymbolAddress((void**)&p_WcmbT, g_WcmbT);

    cudaFuncSetAttribute(gemm_tc<0>, cudaFuncAttributeMaxDynamicSharedMemorySize, GEMM_SMEM);
    cudaFuncSetAttribute(gemm_tc<1>, cudaFuncAttributeMaxDynamicSharedMemorySize, GEMM_SMEM);
    cudaFuncSetAttribute(mha2_kernel, cudaFuncAttributeMaxDynamicSharedMemorySize, MHA2_SMEM);
    cudaFuncSetAttribute(attn2_kernel, cudaFuncAttributeMaxDynamicSharedMemorySize, ATT2_SMEM);
    cudaFuncSetAttribute(ode_kernel, cudaFuncAttributeMaxDynamicSharedMemorySize, ODE_SMEM);

    // --- prep ---
    prep_q<<<2, DM>>>(in_proj_w, in_proj_b, time_b, p_q2);
    prep_G<<<640, 256>>>(in_proj_w, in_proj_b, out_proj_w, out_proj_b,
                         outfn_w, outfn_b, attn_wq, attn_wv, merge_w,
                         p_G3, p_b3, p_WcmbT);

    // --- main pipeline ---
    mha2_kernel<<<BS, 256, MHA2_SMEM>>>(nids, hist_nids, anon, eids, hist_ts, dirs,
                                        node_feat, edge_feat, anony_emb, time_w, time_b,
                                        p_q2, p_wctx, p_last);
    // qh = wctx @ G3^T + b3   (4096 x 128, K=1280)
    gemm_tc<0><<<dim3(1, BS/128), 256, GEMM_SMEM>>>(
        p_wctx, 2*DM, p_G3, 2*DM, p_b3, p_qh, NF, BS, NF, 2*DM);
    // qh2 = qh @ attn_wk^T    (4096 x 384, K=128)
    gemm_tc<0><<<dim3(NB3/128, BS/128), 256, GEMM_SMEM>>>(
        p_qh, NF, attn_wk, NF, nullptr, p_qh2, NB3, BS, NB3, NF);
    attn2_kernel<<<BS, 128, ATT2_SMEM>>>(nids, hist_nids, eids, hist_ts,
                                         node_feat, edge_feat, time_w, time_b,
                                         p_qh2, p_A2);
    // hpl = tanh(A2 @ WcmbT^T + merge_b)   (4096 x 128, K=512)
    gemm_tc<1><<<dim3(1, BS/128), 256, GEMM_SMEM>>>(
        p_A2, 512, p_WcmbT, 512, merge_b, p_hpl, NF, BS, NF, 512);
    // gi = last @ gru_w_ih^T + b   (K=512)
    gemm_tc<0><<<dim3(3*NF/128, BS/128), 256, GEMM_SMEM>>>(
        p_last, DIN, gru_w_ih, DIN, gru_b_ih, p_gi, 3*NF, BS, 3*NF, DIN);
    // gh = hpl @ gru_w_hh^T + b    (K=128)
    gemm_tc<0><<<dim3(3*NF/128, BS/128), 256, GEMM_SMEM>>>(
        p_hpl, NF, gru_w_hh, NF, gru_b_hh, p_gh, 3*NF, BS, 3*NF, NF);
    gru_kernel<<<(BS*NF + 255)/256, 256>>>(p_gi, p_gh, p_hpl, p_hpr);
    ode_kernel<<<BS, 128, ODE_SMEM>>>(p_hpr, ode_w, ode_b, tnode_w, tnode_b, hist_ts, out);
}